// round 14
// baseline (speedup 1.0000x reference)
#include <cuda_runtime.h>
#include <cuda_fp16.h>
#include <cstdint>

#define B_    64
#define P_    49
#define ENC_  1280
#define T_    25
#define V_    10000
#define E_    512
#define H_    1024
#define A_    512
#define G4_   4096
#define NCAT  4608           /* 4*H + A */
#define WIH_LD 1792

#define BK 64
#define STG64  4
#define STG128 3
#define SMEM_BYTES 98304     /* = 4*(64+128)*64*2 = 3*(128+128)*64*2 */

// swizzled smem offset (halves): row r, 16B-chunk c (0..7)
__device__ __forceinline__ int sw(int r, int c) {
    return r * 64 + (((c ^ r) & 7) << 3) + ((c & ~7) << 3);
}

// ---------------- static scratch ----------------
__device__ __align__(16) __half g_Wout [V_ * H_];
__device__ __align__(16) __half g_Weatt[A_ * ENC_];
__device__ __align__(16) __half g_Wh0c0[2048 * ENC_];
__device__ __align__(16) __half g_Wihx [G4_ * E_];
__device__ __align__(16) __half g_Wihc [G4_ * ENC_];
__device__ __align__(16) __half g_Wcat [NCAT * H_];
__device__ __align__(16) __half g_ench [(B_ * P_ + 64) * ENC_];
__device__ __align__(16) __half g_meanh[B_ * ENC_];
__device__ __align__(16) __half g_embX [(T_ - 1) * B_ * E_];
__device__ __align__(16) __half g_hall [(T_ * B_ + 64) * H_];   /* +64 pad rows */
__device__ __align__(16) __half g_encW [B_ * P_ * G4_];
__device__ __align__(16) __half g_gatesX[(T_ - 1) * B_ * G4_];
__device__ __align__(16) __half g_att1h[B_ * P_ * A_];
__device__ __align__(16) float  g_cbuf [2 * B_ * H_];
__device__ __align__(16) float  g_ghp  [4 * B_ * NCAT];
__device__ __align__(16) float  g_bh0c0[2048];
__device__ __align__(16) float  g_bsum [G4_];

// ---------------- setup conversions (4 elems / thread) ----------------
#define T0 (V_ * H_)
#define T1 (T0 + A_ * ENC_)
#define T2 (T1 + 2048 * ENC_)
#define T3 (T2 + B_ * P_ * ENC_)
#define T4 (T3 + G4_ * E_)
#define T5 (T4 + G4_ * ENC_)
#define T6 (T5 + NCAT * H_)
#define T7 (T6 + 2048)
#define T8 (T7 + G4_)

__device__ __forceinline__ void cvt4(__half* d, const float* s) {
    float4 v = *(const float4*)s;
    __half2* d2 = (__half2*)d;
    d2[0] = __floats2half2_rn(v.x, v.y);
    d2[1] = __floats2half2_rn(v.z, v.w);
}

__global__ void cvt_all(const float* __restrict__ Wo, const float* __restrict__ We,
                        const float* __restrict__ Wh0, const float* __restrict__ Wc0,
                        const float* __restrict__ enc, const float* __restrict__ Wih,
                        const float* __restrict__ Whh, const float* __restrict__ Wd,
                        const float* __restrict__ bh0, const float* __restrict__ bc0,
                        const float* __restrict__ bih, const float* __restrict__ bhh)
{
    int i = (blockIdx.x * 256 + threadIdx.x) * 4;
    if (i >= T8) return;
    if (i < T0) { cvt4(g_Wout + i, Wo + i); return; }
    if (i < T1) { cvt4(g_Weatt + (i - T0), We + (i - T0)); return; }
    if (i < T2) {
        int j = i - T1; int r = j / ENC_, c = j % ENC_;
        cvt4(g_Wh0c0 + j, (r < 1024 ? Wh0 + (size_t)r * ENC_ : Wc0 + (size_t)(r - 1024) * ENC_) + c);
        return;
    }
    if (i < T3) { cvt4(g_ench + (i - T2), enc + (i - T2)); return; }
    if (i < T4) {
        int j = i - T3; int r = j / E_, c = j % E_;
        cvt4(g_Wihx + j, Wih + (size_t)r * WIH_LD + c);
        return;
    }
    if (i < T5) {
        int j = i - T4; int r = j / ENC_, c = j % ENC_;
        cvt4(g_Wihc + j, Wih + (size_t)r * WIH_LD + E_ + c);
        return;
    }
    if (i < T6) {
        int j = i - T5; int r = j / H_, c = j % H_;
        cvt4(g_Wcat + j, (r < G4_ ? Whh + (size_t)r * H_ : Wd + (size_t)(r - G4_) * H_) + c);
        return;
    }
    if (i < T7) {
        int j = i - T6;
        *(float4*)(g_bh0c0 + j) = (j < 1024) ? *(const float4*)(bh0 + j)
                                             : *(const float4*)(bc0 + (j - 1024));
        return;
    }
    int j = i - T7;
    float4 a = *(const float4*)(bih + j), bv = *(const float4*)(bhh + j);
    *(float4*)(g_bsum + j) = make_float4(a.x + bv.x, a.y + bv.y, a.z + bv.z, a.w + bv.w);
}

__global__ void mean_kernel(const float* __restrict__ enc) {
    int i = blockIdx.x * blockDim.x + threadIdx.x;
    if (i >= B_ * ENC_) return;
    int b = i / ENC_, e = i % ENC_;
    const float* p = enc + (size_t)b * P_ * ENC_ + e;
    float s = 0.f;
#pragma unroll 7
    for (int k = 0; k < P_; k++) s += p[k * ENC_];
    g_meanh[i] = __float2half(s * (1.0f / P_));
}

__global__ void embx_kernel(const int* __restrict__ captions,
                            const float* __restrict__ embed)
{
    int i = (blockIdx.x * 256 + threadIdx.x) * 4;
    if (i >= (T_ - 1) * B_ * E_) return;
    int r = i / E_, c = i % E_;
    int t = r / B_, b = r % B_;
    int cap = captions[b * T_ + t];
    cvt4(g_embX + i, embed + (size_t)cap * E_ + c);
}

// ============ gemm64: 64x128 tile, 256 thr (M=64 GEMMs) =====================
__device__ __forceinline__ void issue_tile64(
    const __half* __restrict__ A, int lda,
    const __half* __restrict__ B, int ldb,
    int bm, int bn, int N, int kt,
    __half* as, __half* bs, int tid)
{
#pragma unroll
    for (int i = 0; i < 2; i++) {
        int idx = i * 256 + tid;
        int r = idx >> 3, c = idx & 7;
        uint32_t da = (uint32_t)__cvta_generic_to_shared(as + sw(r, c));
        const __half* pa = A + (size_t)(bm + r) * lda + kt + c * 8;
        asm volatile("cp.async.cg.shared.global [%0], [%1], 16;" :: "r"(da), "l"(pa));
    }
#pragma unroll
    for (int i = 0; i < 4; i++) {
        int idx = i * 256 + tid;
        int r = idx >> 3, c = idx & 7;
        int n = bn + r;
        uint32_t db = (uint32_t)__cvta_generic_to_shared(bs + sw(r, c));
        const __half* pb = B + (size_t)(n < N ? n : 0) * ldb + kt + c * 8;
        int sz = (n < N) ? 16 : 0;
        asm volatile("cp.async.cg.shared.global [%0], [%1], 16, %2;" :: "r"(db), "l"(pb), "r"(sz));
    }
    asm volatile("cp.async.commit_group;");
}

// mode: 0 = fp32 split-K partials, 3 = h0c0 split
__device__ __forceinline__ void gemm_core64(
    const __half* __restrict__ A, int lda,
    const __half* __restrict__ Bm, int ldb,
    float* __restrict__ Cf, int ldc, int partStride, int N, int kChunk,
    int bm, int by, int z, int mode)
{
    extern __shared__ __half sm[];
    __half* Asm = sm;
    __half* Bsm = sm + STG64 * 64 * 64;

    const int tid = threadIdx.x;
    const int warp = tid >> 5, lane = tid & 31;
    const int wm = warp >> 2, wn = warp & 3;
    const int bn = by * 128;
    const int k0 = z * kChunk;
    const int nk = kChunk / BK;

    float acc[2][4][4];
#pragma unroll
    for (int i = 0; i < 2; i++)
#pragma unroll
        for (int j = 0; j < 4; j++)
#pragma unroll
            for (int q = 0; q < 4; q++) acc[i][j][q] = 0.f;

    const int a_row_l = (lane & 7) + ((lane >> 3) & 1) * 8;
    const int a_chk_l = (lane >> 4) & 1;
    const int b_row_l = (lane & 7) + ((lane >> 4) & 1) * 8;
    const int b_chk_l = (lane >> 3) & 1;

#pragma unroll
    for (int s = 0; s < STG64 - 1; s++) {
        if (s < nk) issue_tile64(A, lda, Bm, ldb, bm, bn, N, k0 + s * BK,
                                 Asm + s * 64 * 64, Bsm + s * 128 * 64, tid);
        else asm volatile("cp.async.commit_group;");
    }

    for (int i = 0; i < nk; i++) {
        asm volatile("cp.async.wait_group %0;" :: "n"(STG64 - 2));
        __syncthreads();

        int ntile = i + STG64 - 1;
        if (ntile < nk) {
            int slot = ntile % STG64;
            issue_tile64(A, lda, Bm, ldb, bm, bn, N, k0 + ntile * BK,
                         Asm + slot * 64 * 64, Bsm + slot * 128 * 64, tid);
        } else {
            asm volatile("cp.async.commit_group;");
        }

        const __half* at = Asm + (i % STG64) * 64 * 64;
        const __half* bt = Bsm + (i % STG64) * 128 * 64;

#pragma unroll
        for (int ks = 0; ks < 4; ks++) {
            uint32_t a[2][4], b[4][2];
#pragma unroll
            for (int mt = 0; mt < 2; mt++) {
                int row = wm * 32 + mt * 16 + a_row_l;
                uint32_t ad = (uint32_t)__cvta_generic_to_shared(at + sw(row, ks * 2 + a_chk_l));
                asm volatile("ldmatrix.sync.aligned.m8n8.x4.shared.b16 {%0,%1,%2,%3}, [%4];"
                             : "=r"(a[mt][0]), "=r"(a[mt][1]), "=r"(a[mt][2]), "=r"(a[mt][3])
                             : "r"(ad));
            }
#pragma unroll
            for (int ntp = 0; ntp < 2; ntp++) {
                int row = wn * 32 + ntp * 16 + b_row_l;
                uint32_t bd = (uint32_t)__cvta_generic_to_shared(bt + sw(row, ks * 2 + b_chk_l));
                asm volatile("ldmatrix.sync.aligned.m8n8.x4.shared.b16 {%0,%1,%2,%3}, [%4];"
                             : "=r"(b[2 * ntp][0]), "=r"(b[2 * ntp][1]),
                               "=r"(b[2 * ntp + 1][0]), "=r"(b[2 * ntp + 1][1])
                             : "r"(bd));
            }
#pragma unroll
            for (int mt = 0; mt < 2; mt++)
#pragma unroll
                for (int nt = 0; nt < 4; nt++)
                    asm volatile(
                        "mma.sync.aligned.m16n8k16.row.col.f32.f16.f16.f32 "
                        "{%0,%1,%2,%3}, {%4,%5,%6,%7}, {%8,%9}, {%0,%1,%2,%3};"
                        : "+f"(acc[mt][nt][0]), "+f"(acc[mt][nt][1]),
                          "+f"(acc[mt][nt][2]), "+f"(acc[mt][nt][3])
                        : "r"(a[mt][0]), "r"(a[mt][1]), "r"(a[mt][2]), "r"(a[mt][3]),
                          "r"(b[nt][0]), "r"(b[nt][1]));
        }
    }

    float* Cz = Cf + (size_t)z * partStride;
#pragma unroll
    for (int mt = 0; mt < 2; mt++) {
        int r0 = bm + wm * 32 + mt * 16 + (lane >> 2);
        int r1 = r0 + 8;
#pragma unroll
        for (int nt = 0; nt < 4; nt++) {
            int cg = bn + wn * 32 + nt * 8 + (lane & 3) * 2;
            float v00 = acc[mt][nt][0], v01 = acc[mt][nt][1];
            float v10 = acc[mt][nt][2], v11 = acc[mt][nt][3];
            if (mode == 3) {
#pragma unroll
                for (int e = 0; e < 2; e++) {
                    int c = cg + e;
                    float va = e ? v01 : v00, vb = e ? v11 : v10;
                    float bb = g_bh0c0[c];
                    if (c < 1024) {
                        g_hall[r0 * H_ + c] = __float2half(va + bb);
                        g_hall[r1 * H_ + c] = __float2half(vb + bb);
                    } else {
                        g_cbuf[r0 * H_ + c - 1024] = va + bb;
                        g_cbuf[r1 * H_ + c - 1024] = vb + bb;
                    }
                }
            } else {
                if (cg < N) {
                    Cz[(size_t)r0 * ldc + cg] = v00;
                    Cz[(size_t)r1 * ldc + cg] = v10;
                }
                if (cg + 1 < N) {
                    Cz[(size_t)r0 * ldc + cg + 1] = v01;
                    Cz[(size_t)r1 * ldc + cg + 1] = v11;
                }
            }
        }
    }
}

// ============ gemm128: 128x128 tile, 256 thr, warp-tile 32x64 ===============
__device__ __forceinline__ void issue_tile128(
    const __half* __restrict__ A, int lda,
    const __half* __restrict__ B, int ldb,
    int bm, int bn, int N, int kt,
    __half* as, __half* bs, int tid)
{
#pragma unroll
    for (int i = 0; i < 4; i++) {
        int idx = i * 256 + tid;
        int r = idx >> 3, c = idx & 7;
        uint32_t da = (uint32_t)__cvta_generic_to_shared(as + sw(r, c));
        const __half* pa = A + (size_t)(bm + r) * lda + kt + c * 8;
        asm volatile("cp.async.cg.shared.global [%0], [%1], 16;" :: "r"(da), "l"(pa));
    }
#pragma unroll
    for (int i = 0; i < 4; i++) {
        int idx = i * 256 + tid;
        int r = idx >> 3, c = idx & 7;
        int n = bn + r;
        uint32_t db = (uint32_t)__cvta_generic_to_shared(bs + sw(r, c));
        const __half* pb = B + (size_t)(n < N ? n : 0) * ldb + kt + c * 8;
        int sz = (n < N) ? 16 : 0;
        asm volatile("cp.async.cg.shared.global [%0], [%1], 16, %2;" :: "r"(db), "l"(pb), "r"(sz));
    }
    asm volatile("cp.async.commit_group;");
}

// mode: 1 = fp16 out (+bias), 2 = logits capmap (+bias, rowoff = global row base)
__device__ __forceinline__ void gemm_core128(
    const __half* __restrict__ A, int lda,
    const __half* __restrict__ Bm, int ldb,
    const float* __restrict__ bias,
    float* __restrict__ Cf, __half* __restrict__ Ch,
    int ldc, int M, int N, int K,
    int bm, int by, int mode, int rowoff)
{
    extern __shared__ __half sm[];
    __half* Asm = sm;
    __half* Bsm = sm + STG128 * 128 * 64;

    const int tid = threadIdx.x;
    const int warp = tid >> 5, lane = tid & 31;
    const int wm = warp >> 1, wn = warp & 1;
    const int bn = by * 128;
    const int nk = K / BK;

    float acc[2][8][4];
#pragma unroll
    for (int i = 0; i < 2; i++)
#pragma unroll
        for (int j = 0; j < 8; j++)
#pragma unroll
            for (int q = 0; q < 4; q++) acc[i][j][q] = 0.f;

    const int a_row_l = (lane & 7) + ((lane >> 3) & 1) * 8;
    const int a_chk_l = (lane >> 4) & 1;
    const int b_row_l = (lane & 7) + ((lane >> 4) & 1) * 8;
    const int b_chk_l = (lane >> 3) & 1;

#pragma unroll
    for (int s = 0; s < STG128 - 1; s++) {
        if (s < nk) issue_tile128(A, lda, Bm, ldb, bm, bn, N, s * BK,
                                  Asm + s * 128 * 64, Bsm + s * 128 * 64, tid);
        else asm volatile("cp.async.commit_group;");
    }

    for (int i = 0; i < nk; i++) {
        asm volatile("cp.async.wait_group %0;" :: "n"(STG128 - 2));
        __syncthreads();

        int ntile = i + STG128 - 1;
        if (ntile < nk) {
            int slot = ntile % STG128;
            issue_tile128(A, lda, Bm, ldb, bm, bn, N, ntile * BK,
                          Asm + slot * 128 * 64, Bsm + slot * 128 * 64, tid);
        } else {
            asm volatile("cp.async.commit_group;");
        }

        const __half* at = Asm + (i % STG128) * 128 * 64;
        const __half* bt = Bsm + (i % STG128) * 128 * 64;

#pragma unroll
        for (int ks = 0; ks < 4; ks++) {
            uint32_t a[2][4], b[8][2];
#pragma unroll
            for (int mt = 0; mt < 2; mt++) {
                int row = wm * 32 + mt * 16 + a_row_l;
                uint32_t ad = (uint32_t)__cvta_generic_to_shared(at + sw(row, ks * 2 + a_chk_l));
                asm volatile("ldmatrix.sync.aligned.m8n8.x4.shared.b16 {%0,%1,%2,%3}, [%4];"
                             : "=r"(a[mt][0]), "=r"(a[mt][1]), "=r"(a[mt][2]), "=r"(a[mt][3])
                             : "r"(ad));
            }
#pragma unroll
            for (int ntp = 0; ntp < 4; ntp++) {
                int row = wn * 64 + ntp * 16 + b_row_l;
                uint32_t bd = (uint32_t)__cvta_generic_to_shared(bt + sw(row, ks * 2 + b_chk_l));
                asm volatile("ldmatrix.sync.aligned.m8n8.x4.shared.b16 {%0,%1,%2,%3}, [%4];"
                             : "=r"(b[2 * ntp][0]), "=r"(b[2 * ntp][1]),
                               "=r"(b[2 * ntp + 1][0]), "=r"(b[2 * ntp + 1][1])
                             : "r"(bd));
            }
#pragma unroll
            for (int mt = 0; mt < 2; mt++)
#pragma unroll
                for (int nt = 0; nt < 8; nt++)
                    asm volatile(
                        "mma.sync.aligned.m16n8k16.row.col.f32.f16.f16.f32 "
                        "{%0,%1,%2,%3}, {%4,%5,%6,%7}, {%8,%9}, {%0,%1,%2,%3};"
                        : "+f"(acc[mt][nt][0]), "+f"(acc[mt][nt][1]),
                          "+f"(acc[mt][nt][2]), "+f"(acc[mt][nt][3])
                        : "r"(a[mt][0]), "r"(a[mt][1]), "r"(a[mt][2]), "r"(a[mt][3]),
                          "r"(b[nt][0]), "r"(b[nt][1]));
        }
    }

#pragma unroll
    for (int mt = 0; mt < 2; mt++) {
        int r0 = bm + wm * 32 + mt * 16 + (lane >> 2);
        int r1 = r0 + 8;
#pragma unroll
        for (int nt = 0; nt < 8; nt++) {
            int cg = bn + wn * 64 + nt * 8 + (lane & 3) * 2;
            float bv0 = 0.f, bv1 = 0.f;
            if (bias) {
                if (cg < N) bv0 = bias[cg];
                if (cg + 1 < N) bv1 = bias[cg + 1];
            }
            float v00 = acc[mt][nt][0] + bv0, v01 = acc[mt][nt][1] + bv1;
            float v10 = acc[mt][nt][2] + bv0, v11 = acc[mt][nt][3] + bv1;
            if (mode == 2) {
                int gr0 = rowoff + r0, gr1 = rowoff + r1;
                float* p0 = Cf + (size_t)(gr0 & 63) * ((T_ - 1) * V_) + (size_t)(gr0 >> 6) * V_;
                float* p1 = Cf + (size_t)(gr1 & 63) * ((T_ - 1) * V_) + (size_t)(gr1 >> 6) * V_;
                if (cg < N) {
                    if (r0 < M) p0[cg] = v00;
                    if (r1 < M) p1[cg] = v10;
                }
                if (cg + 1 < N) {
                    if (r0 < M) p0[cg + 1] = v01;
                    if (r1 < M) p1[cg + 1] = v11;
                }
            } else {
                if (cg < N) {
                    if (r0 < M) Ch[(size_t)r0 * ldc + cg] = __float2half(v00);
                    if (r1 < M) Ch[(size_t)r1 * ldc + cg] = __float2half(v10);
                }
                if (cg + 1 < N) {
                    if (r0 < M) Ch[(size_t)r0 * ldc + cg + 1] = __float2half(v01);
                    if (r1 < M) Ch[(size_t)r1 * ldc + cg + 1] = __float2half(v11);
                }
            }
        }
    }
}

// setup: h0c0 [16] + att1 [100] + gatesX [384] + encW [800] = 1300 blocks
#define CB0 16
#define CB1 (CB0 + 25 * 4)
#define CB2 (CB1 + 12 * 32)
#define CB3 (CB2 + 25 * 32)

__global__ void __launch_bounds__(256, 2)
setup_combo(const float* __restrict__ b_eatt)
{
    int bi = blockIdx.x;
    if (bi < CB0) {
        gemm_core64(g_meanh, ENC_, g_Wh0c0, ENC_, nullptr,
                    0, 0, 2048, ENC_, 0, bi, 0, 3);
    } else if (bi < CB1) {
        int i = bi - CB0;
        gemm_core128(g_ench, ENC_, g_Weatt, ENC_, b_eatt, nullptr, g_att1h,
                     A_, B_ * P_, A_, ENC_, (i % 25) * 128, i / 25, 1, 0);
    } else if (bi < CB2) {
        int i = bi - CB1;
        gemm_core128(g_embX, E_, g_Wihx, E_, nullptr, nullptr, g_gatesX,
                     G4_, (T_ - 1) * B_, G4_, E_, (i % 12) * 128, i / 12, 1, 0);
    } else {
        int i = bi - CB2;
        gemm_core128(g_ench, ENC_, g_Wihc, ENC_, nullptr, nullptr, g_encW,
                     G4_, B_ * P_, G4_, ENC_, (i % 25) * 128, i / 25, 1, 0);
    }
}

// per-step fused GEMM: h_t @ [W_hh | W_datt]^T -> ghp partials (split-K 4)
__global__ void __launch_bounds__(256, 2)
hw_kernel(const __half* __restrict__ h)
{
    gemm_core64(h, H_, g_Wcat, H_, g_ghp,
                NCAT, B_ * NCAT, NCAT, H_ / 4, 0, blockIdx.x, blockIdx.y, 0);
}

// ---------------- gatelstm body (128 blocks, 2 j's/thread via half2) -------
__device__ void gatelstm_body2(int z, int b, int t,
                               const float* __restrict__ b_datt,
                               const float* __restrict__ W_fatt,
                               const float* __restrict__ b_fatt,
                               float* att2s, float* alpha)
{
    const int tid = threadIdx.x;
    const int warp = tid >> 5, lane = tid & 31;

    // att2 reduce (4 split-K partials)
    for (int a = tid; a < A_; a += 256) {
        float s = b_datt[a];
#pragma unroll
        for (int zz = 0; zz < 4; zz++)
            s += g_ghp[(size_t)zz * B_ * NCAT + b * NCAT + G4_ + a];
        att2s[a] = s;
    }
    __syncthreads();

    // e_p (att1 fp16, half2 loads)
    const __half2* att1b2 = (const __half2*)(g_att1h + (size_t)b * P_ * A_);
#pragma unroll 7
    for (int p = warp; p < P_; p += 8) {
        float s = 0.f;
#pragma unroll
        for (int a2 = lane; a2 < 256; a2 += 32) {
            float2 v = __half22float2(att1b2[p * 256 + a2]);
            float v0 = v.x + att2s[2 * a2];
            float v1 = v.y + att2s[2 * a2 + 1];
            s += fmaxf(v0, 0.f) * W_fatt[2 * a2] + fmaxf(v1, 0.f) * W_fatt[2 * a2 + 1];
        }
#pragma unroll
        for (int o = 16; o; o >>= 1) s += __shfl_xor_sync(0xffffffffu, s, o);
        if (lane == 0) alpha[p] = s + b_fatt[0];
    }
    __syncthreads();

    if (warp == 0) {
        float v0 = (lane < P_) ? alpha[lane] : -1e30f;
        float v1 = (lane + 32 < P_) ? alpha[lane + 32] : -1e30f;
        float m = fmaxf(v0, v1);
#pragma unroll
        for (int o = 16; o; o >>= 1) m = fmaxf(m, __shfl_xor_sync(0xffffffffu, m, o));
        float e0 = (lane < P_) ? __expf(v0 - m) : 0.f;
        float e1 = (lane + 32 < P_) ? __expf(v1 - m) : 0.f;
        float s = e0 + e1;
#pragma unroll
        for (int o = 16; o; o >>= 1) s += __shfl_xor_sync(0xffffffffu, s, o);
        float inv = 1.0f / s;
        if (lane < P_) alpha[lane] = e0 * inv;
        if (lane + 32 < P_) alpha[lane + 32] = e1 * inv;
    }
    __syncthreads();

    // gates: j0 = z*512 + tid*2, thread handles j0 and j0+1 for all 4 gates
    const int j0 = z * 512 + tid * 2;
    const int jj = j0 >> 1;   // half2 index within a 1024-wide gate segment
    const __half2* encWb = (const __half2*)(g_encW + (size_t)b * P_ * G4_);
    float gi0 = 0.f, gi1 = 0.f, gf0 = 0.f, gf1 = 0.f;
    float gg0 = 0.f, gg1 = 0.f, go0 = 0.f, go1 = 0.f;
#pragma unroll 7
    for (int p = 0; p < P_; p++) {
        const __half2* row = encWb + (size_t)p * (G4_ / 2);
        float ap = alpha[p];
        float2 w;
        w = __half22float2(row[jj]);        gi0 += ap * w.x; gi1 += ap * w.y;
        w = __half22float2(row[512 + jj]);  gf0 += ap * w.x; gf1 += ap * w.y;
        w = __half22float2(row[1024 + jj]); gg0 += ap * w.x; gg1 += ap * w.y;
        w = __half22float2(row[1536 + jj]); go0 += ap * w.x; go1 += ap * w.y;
    }
    const __half2* gx2 = (const __half2*)(g_gatesX + ((size_t)t * B_ + b) * G4_);
    {
        float2 w;
        w = __half22float2(gx2[jj]);        gi0 += w.x; gi1 += w.y;
        w = __half22float2(gx2[512 + jj]);  gf0 += w.x; gf1 += w.y;
        w = __half22float2(gx2[1024 + jj]); gg0 += w.x; gg1 += w.y;
        w = __half22float2(gx2[1536 + jj]); go0 += w.x; go1 += w.y;
        float2 bb;
        bb = *(const float2*)(g_bsum + j0);            gi0 += bb.x; gi1 += bb.y;
        bb = *(const float2*)(g_bsum + H_ + j0);       gf0 += bb.x; gf1 += bb.y;
        bb = *(const float2*)(g_bsum + 2 * H_ + j0);   gg0 += bb.x; gg1 += bb.y;
        bb = *(const float2*)(g_bsum + 3 * H_ + j0);   go0 += bb.x; go1 += bb.y;
    }
#pragma unroll
    for (int zz = 0; zz < 4; zz++) {
        const float* gp = g_ghp + (size_t)zz * B_ * NCAT + b * NCAT;
        float2 q;
        q = *(const float2*)(gp + j0);          gi0 += q.x; gi1 += q.y;
        q = *(const float2*)(gp + H_ + j0);     gf0 += q.x; gf1 += q.y;
        q = *(const float2*)(gp + 2 * H_ + j0); gg0 += q.x; gg1 += q.y;
        q = *(const float2*)(gp + 3 * H_ + j0); go0 += q.x; go1 += q.y;
    }

    const float* c_cur = g_cbuf + (t & 1) * B_ * H_;
    float* c_nxt = g_cbuf + ((t + 1) & 1) * B_ * H_;
    __half* h_nxt = g_hall + (size_t)(t + 1) * B_ * H_;
    float2 cc = *(const float2*)(c_cur + b * H_ + j0);
    float si0 = 1.f / (1.f + __expf(-gi0)), si1 = 1.f / (1.f + __expf(-gi1));
    float sf0 = 1.f / (1.f + __expf(-gf0)), sf1 = 1.f / (1.f + __expf(-gf1));
    float so0 = 1.f / (1.f + __expf(-go0)), so1 = 1.f / (1.f + __expf(-go1));
    float tg0 = tanhf(gg0), tg1 = tanhf(gg1);
    float c0 = sf0 * cc.x + si0 * tg0;
    float c1 = sf1 * cc.y + si1 * tg1;
    *(float2*)(c_nxt + b * H_ + j0) = make_float2(c0, c1);
    *(__half2*)(h_nxt + b * H_ + j0) =
        __floats2half2_rn(so0 * tanhf(c0), so1 * tanhf(c1));
}

// ---------------- step2: gatelstm (128 blocks) + logits(h_t) rides (79) ----
__global__ void __launch_bounds__(256, 2)
step2_kernel(const float* __restrict__ b_datt,
             const float* __restrict__ W_fatt,
             const float* __restrict__ b_fatt,
             const float* __restrict__ b_out,
             float* __restrict__ out,
             int t)
{
    extern __shared__ __half sm[];
    int bi = blockIdx.x;
    if (bi < 128) {
        float* att2s = (float*)sm;
        float* alpha = att2s + A_;
        gatelstm_body2(bi & 1, bi >> 1, t, b_datt, W_fatt, b_fatt, att2s, alpha);
    } else if (t >= 1) {
        // logits tile for h_t (out row t-1)
        gemm_core128(g_hall + (size_t)t * B_ * H_, H_, g_Wout, H_, b_out, out, nullptr,
                     0, 64, V_, H_, 0, bi - 128, 2, (t - 1) * 64);
    }
}

// final logits for h_24 (out row 23)
__global__ void __launch_bounds__(256, 2)
final_logits(const float* __restrict__ b_out, float* __restrict__ out)
{
    gemm_core128(g_hall + (size_t)(T_ - 1) * B_ * H_, H_, g_Wout, H_, b_out, out, nullptr,
                 0, 64, V_, H_, 0, blockIdx.x, 2, (T_ - 2) * 64);
}

// ---------------- host ----------------
extern "C" void kernel_launch(void* const* d_in, const int* in_sizes, int n_in,
                              void* d_out, int out_size)
{
    const float* enc    = (const float*)d_in[0];
    const int*   caps   = (const int*)  d_in[1];
    const float* embed  = (const float*)d_in[2];
    const float* W_eatt = (const float*)d_in[3];
    const float* b_eatt = (const float*)d_in[4];
    const float* W_datt = (const float*)d_in[5];
    const float* b_datt = (const float*)d_in[6];
    const float* W_fatt = (const float*)d_in[7];
    const float* b_fatt = (const float*)d_in[8];
    const float* W_ih   = (const float*)d_in[9];
    const float* b_ih   = (const float*)d_in[10];
    const float* W_hh   = (const float*)d_in[11];
    const float* b_hh   = (const float*)d_in[12];
    const float* W_h0   = (const float*)d_in[13];
    const float* b_h0   = (const float*)d_in[14];
    const float* W_c0   = (const float*)d_in[15];
    const float* b_c0   = (const float*)d_in[16];
    const float* W_out  = (const float*)d_in[17];
    const float* b_out  = (const float*)d_in[18];
    float* out = (float*)d_out;

    cudaFuncSetAttribute(setup_combo, cudaFuncAttributeMaxDynamicSharedMemorySize, SMEM_BYTES);
    cudaFuncSetAttribute(hw_kernel, cudaFuncAttributeMaxDynamicSharedMemorySize, SMEM_BYTES);
    cudaFuncSetAttribute(step2_kernel, cudaFuncAttributeMaxDynamicSharedMemorySize, SMEM_BYTES);
    cudaFuncSetAttribute(final_logits, cudaFuncAttributeMaxDynamicSharedMemorySize, SMEM_BYTES);

    void* hall_p = nullptr;
    cudaGetSymbolAddress(&hall_p, g_hall);
    __half* hall = (__half*)hall_p;

    // ---- one-time setup ----
    mean_kernel<<<(B_ * ENC_ + 255) / 256, 256>>>(enc);
    cvt_all<<<(T8 / 4 + 255) / 256, 256>>>(W_out, W_eatt, W_h0, W_c0, enc, W_ih, W_hh,
                                           W_datt, b_h0, b_c0, b_ih, b_hh);
    embx_kernel<<<((T_ - 1) * B_ * E_ / 4 + 255) / 256, 256>>>(caps, embed);

    setup_combo<<<CB3, 256, SMEM_BYTES>>>(b_eatt);

    // ---- recurrent loop: 2 launches per step; logits rides step2 ----
    for (int t = 0; t < T_ - 1; t++) {
        hw_kernel<<<dim3(36, 4, 1), 256, SMEM_BYTES>>>(hall + (size_t)t * B_ * H_);
        step2_kernel<<<128 + 79, 256, SMEM_BYTES>>>(b_datt, W_fatt, b_fatt, b_out, out, t);
    }

    // ---- final logits for h_24 ----
    final_logits<<<79, 256, SMEM_BYTES>>>(b_out, out);
}

// round 15
// speedup vs baseline: 1.6005x; 1.6005x over previous
#include <cuda_runtime.h>
#include <cuda_fp16.h>
#include <cstdint>

#define B_    64
#define P_    49
#define ENC_  1280
#define T_    25
#define V_    10000
#define E_    512
#define H_    1024
#define A_    512
#define G4_   4096
#define NCAT  4608           /* 4*H + A */
#define WIH_LD 1792

#define BK 64
#define STG64  4
#define STG128 3
#define SMEM_BYTES 98304     /* = 4*(64+128)*64*2 = 3*(128+128)*64*2 */

// swizzled smem offset (halves): row r, 16B-chunk c (0..7)
__device__ __forceinline__ int sw(int r, int c) {
    return r * 64 + (((c ^ r) & 7) << 3) + ((c & ~7) << 3);
}

// ---------------- static scratch ----------------
__device__ __align__(16) __half g_Wout [V_ * H_];
__device__ __align__(16) __half g_Weatt[A_ * ENC_];
__device__ __align__(16) __half g_Wh0c0[2048 * ENC_];
__device__ __align__(16) __half g_Wihx [G4_ * E_];
__device__ __align__(16) __half g_Wihc [G4_ * ENC_];
__device__ __align__(16) __half g_Wcat [NCAT * H_];
__device__ __align__(16) __half g_ench [(B_ * P_ + 64) * ENC_];
__device__ __align__(16) __half g_meanh[B_ * ENC_];
__device__ __align__(16) __half g_embX [(T_ - 1) * B_ * E_];
__device__ __align__(16) __half g_hall [(T_ * B_ + 64) * H_];
__device__ __align__(16) __half g_encW [B_ * P_ * G4_];
__device__ __align__(16) __half g_gatesX[(T_ - 1) * B_ * G4_];
__device__ __align__(16) __half g_att1h[B_ * P_ * A_];
__device__ __align__(16) float  g_cbuf [2 * B_ * H_];
__device__ __align__(16) float  g_ghp  [4 * B_ * NCAT];
__device__ __align__(16) float  g_bh0c0[2048];
__device__ __align__(16) float  g_bsum [G4_];

// ---------------- setup conversions (4 elems / thread) ----------------
#define T0 (V_ * H_)
#define T1 (T0 + A_ * ENC_)
#define T2 (T1 + 2048 * ENC_)
#define T3 (T2 + B_ * P_ * ENC_)
#define T4 (T3 + G4_ * E_)
#define T5 (T4 + G4_ * ENC_)
#define T6 (T5 + NCAT * H_)
#define T7 (T6 + 2048)
#define T8 (T7 + G4_)

__device__ __forceinline__ void cvt4(__half* d, const float* s) {
    float4 v = *(const float4*)s;
    __half2* d2 = (__half2*)d;
    d2[0] = __floats2half2_rn(v.x, v.y);
    d2[1] = __floats2half2_rn(v.z, v.w);
}

__global__ void cvt_all(const float* __restrict__ Wo, const float* __restrict__ We,
                        const float* __restrict__ Wh0, const float* __restrict__ Wc0,
                        const float* __restrict__ enc, const float* __restrict__ Wih,
                        const float* __restrict__ Whh, const float* __restrict__ Wd,
                        const float* __restrict__ bh0, const float* __restrict__ bc0,
                        const float* __restrict__ bih, const float* __restrict__ bhh)
{
    int i = (blockIdx.x * 256 + threadIdx.x) * 4;
    if (i >= T8) return;
    if (i < T0) { cvt4(g_Wout + i, Wo + i); return; }
    if (i < T1) { cvt4(g_Weatt + (i - T0), We + (i - T0)); return; }
    if (i < T2) {
        int j = i - T1; int r = j / ENC_, c = j % ENC_;
        cvt4(g_Wh0c0 + j, (r < 1024 ? Wh0 + (size_t)r * ENC_ : Wc0 + (size_t)(r - 1024) * ENC_) + c);
        return;
    }
    if (i < T3) { cvt4(g_ench + (i - T2), enc + (i - T2)); return; }
    if (i < T4) {
        int j = i - T3; int r = j / E_, c = j % E_;
        cvt4(g_Wihx + j, Wih + (size_t)r * WIH_LD + c);
        return;
    }
    if (i < T5) {
        int j = i - T4; int r = j / ENC_, c = j % ENC_;
        cvt4(g_Wihc + j, Wih + (size_t)r * WIH_LD + E_ + c);
        return;
    }
    if (i < T6) {
        int j = i - T5; int r = j / H_, c = j % H_;
        cvt4(g_Wcat + j, (r < G4_ ? Whh + (size_t)r * H_ : Wd + (size_t)(r - G4_) * H_) + c);
        return;
    }
    if (i < T7) {
        int j = i - T6;
        *(float4*)(g_bh0c0 + j) = (j < 1024) ? *(const float4*)(bh0 + j)
                                             : *(const float4*)(bc0 + (j - 1024));
        return;
    }
    int j = i - T7;
    float4 a = *(const float4*)(bih + j), bv = *(const float4*)(bhh + j);
    *(float4*)(g_bsum + j) = make_float4(a.x + bv.x, a.y + bv.y, a.z + bv.z, a.w + bv.w);
}

__global__ void mean_kernel(const float* __restrict__ enc) {
    int i = blockIdx.x * blockDim.x + threadIdx.x;
    if (i >= B_ * ENC_) return;
    int b = i / ENC_, e = i % ENC_;
    const float* p = enc + (size_t)b * P_ * ENC_ + e;
    float s = 0.f;
#pragma unroll 7
    for (int k = 0; k < P_; k++) s += p[k * ENC_];
    g_meanh[i] = __float2half(s * (1.0f / P_));
}

__global__ void embx_kernel(const int* __restrict__ captions,
                            const float* __restrict__ embed)
{
    int i = (blockIdx.x * 256 + threadIdx.x) * 4;
    if (i >= (T_ - 1) * B_ * E_) return;
    int r = i / E_, c = i % E_;
    int t = r / B_, b = r % B_;
    int cap = captions[b * T_ + t];
    cvt4(g_embX + i, embed + (size_t)cap * E_ + c);
}

// ============ gemm64: 64x128 tile, 256 thr (M=64 GEMMs) =====================
__device__ __forceinline__ void issue_tile64(
    const __half* __restrict__ A, int lda,
    const __half* __restrict__ B, int ldb,
    int bm, int bn, int N, int kt,
    __half* as, __half* bs, int tid)
{
#pragma unroll
    for (int i = 0; i < 2; i++) {
        int idx = i * 256 + tid;
        int r = idx >> 3, c = idx & 7;
        uint32_t da = (uint32_t)__cvta_generic_to_shared(as + sw(r, c));
        const __half* pa = A + (size_t)(bm + r) * lda + kt + c * 8;
        asm volatile("cp.async.cg.shared.global [%0], [%1], 16;" :: "r"(da), "l"(pa));
    }
#pragma unroll
    for (int i = 0; i < 4; i++) {
        int idx = i * 256 + tid;
        int r = idx >> 3, c = idx & 7;
        int n = bn + r;
        uint32_t db = (uint32_t)__cvta_generic_to_shared(bs + sw(r, c));
        const __half* pb = B + (size_t)(n < N ? n : 0) * ldb + kt + c * 8;
        int sz = (n < N) ? 16 : 0;
        asm volatile("cp.async.cg.shared.global [%0], [%1], 16, %2;" :: "r"(db), "l"(pb), "r"(sz));
    }
    asm volatile("cp.async.commit_group;");
}

// mode: 0 = fp32 split-K partials, 3 = h0c0 split
__device__ __forceinline__ void gemm_core64(
    const __half* __restrict__ A, int lda,
    const __half* __restrict__ Bm, int ldb,
    float* __restrict__ Cf, int ldc, int partStride, int N, int kChunk,
    int bm, int by, int z, int mode)
{
    extern __shared__ __half sm[];
    __half* Asm = sm;
    __half* Bsm = sm + STG64 * 64 * 64;

    const int tid = threadIdx.x;
    const int warp = tid >> 5, lane = tid & 31;
    const int wm = warp >> 2, wn = warp & 3;
    const int bn = by * 128;
    const int k0 = z * kChunk;
    const int nk = kChunk / BK;

    float acc[2][4][4];
#pragma unroll
    for (int i = 0; i < 2; i++)
#pragma unroll
        for (int j = 0; j < 4; j++)
#pragma unroll
            for (int q = 0; q < 4; q++) acc[i][j][q] = 0.f;

    const int a_row_l = (lane & 7) + ((lane >> 3) & 1) * 8;
    const int a_chk_l = (lane >> 4) & 1;
    const int b_row_l = (lane & 7) + ((lane >> 4) & 1) * 8;
    const int b_chk_l = (lane >> 3) & 1;

#pragma unroll
    for (int s = 0; s < STG64 - 1; s++) {
        if (s < nk) issue_tile64(A, lda, Bm, ldb, bm, bn, N, k0 + s * BK,
                                 Asm + s * 64 * 64, Bsm + s * 128 * 64, tid);
        else asm volatile("cp.async.commit_group;");
    }

    for (int i = 0; i < nk; i++) {
        asm volatile("cp.async.wait_group %0;" :: "n"(STG64 - 2));
        __syncthreads();

        int ntile = i + STG64 - 1;
        if (ntile < nk) {
            int slot = ntile % STG64;
            issue_tile64(A, lda, Bm, ldb, bm, bn, N, k0 + ntile * BK,
                         Asm + slot * 64 * 64, Bsm + slot * 128 * 64, tid);
        } else {
            asm volatile("cp.async.commit_group;");
        }

        const __half* at = Asm + (i % STG64) * 64 * 64;
        const __half* bt = Bsm + (i % STG64) * 128 * 64;

#pragma unroll
        for (int ks = 0; ks < 4; ks++) {
            uint32_t a[2][4], b[4][2];
#pragma unroll
            for (int mt = 0; mt < 2; mt++) {
                int row = wm * 32 + mt * 16 + a_row_l;
                uint32_t ad = (uint32_t)__cvta_generic_to_shared(at + sw(row, ks * 2 + a_chk_l));
                asm volatile("ldmatrix.sync.aligned.m8n8.x4.shared.b16 {%0,%1,%2,%3}, [%4];"
                             : "=r"(a[mt][0]), "=r"(a[mt][1]), "=r"(a[mt][2]), "=r"(a[mt][3])
                             : "r"(ad));
            }
#pragma unroll
            for (int ntp = 0; ntp < 2; ntp++) {
                int row = wn * 32 + ntp * 16 + b_row_l;
                uint32_t bd = (uint32_t)__cvta_generic_to_shared(bt + sw(row, ks * 2 + b_chk_l));
                asm volatile("ldmatrix.sync.aligned.m8n8.x4.shared.b16 {%0,%1,%2,%3}, [%4];"
                             : "=r"(b[2 * ntp][0]), "=r"(b[2 * ntp][1]),
                               "=r"(b[2 * ntp + 1][0]), "=r"(b[2 * ntp + 1][1])
                             : "r"(bd));
            }
#pragma unroll
            for (int mt = 0; mt < 2; mt++)
#pragma unroll
                for (int nt = 0; nt < 4; nt++)
                    asm volatile(
                        "mma.sync.aligned.m16n8k16.row.col.f32.f16.f16.f32 "
                        "{%0,%1,%2,%3}, {%4,%5,%6,%7}, {%8,%9}, {%0,%1,%2,%3};"
                        : "+f"(acc[mt][nt][0]), "+f"(acc[mt][nt][1]),
                          "+f"(acc[mt][nt][2]), "+f"(acc[mt][nt][3])
                        : "r"(a[mt][0]), "r"(a[mt][1]), "r"(a[mt][2]), "r"(a[mt][3]),
                          "r"(b[nt][0]), "r"(b[nt][1]));
        }
    }

    float* Cz = Cf + (size_t)z * partStride;
#pragma unroll
    for (int mt = 0; mt < 2; mt++) {
        int r0 = bm + wm * 32 + mt * 16 + (lane >> 2);
        int r1 = r0 + 8;
#pragma unroll
        for (int nt = 0; nt < 4; nt++) {
            int cg = bn + wn * 32 + nt * 8 + (lane & 3) * 2;
            float v00 = acc[mt][nt][0], v01 = acc[mt][nt][1];
            float v10 = acc[mt][nt][2], v11 = acc[mt][nt][3];
            if (mode == 3) {
#pragma unroll
                for (int e = 0; e < 2; e++) {
                    int c = cg + e;
                    float va = e ? v01 : v00, vb = e ? v11 : v10;
                    float bb = g_bh0c0[c];
                    if (c < 1024) {
                        g_hall[r0 * H_ + c] = __float2half(va + bb);
                        g_hall[r1 * H_ + c] = __float2half(vb + bb);
                    } else {
                        g_cbuf[r0 * H_ + c - 1024] = va + bb;
                        g_cbuf[r1 * H_ + c - 1024] = vb + bb;
                    }
                }
            } else {
                if (cg < N) {
                    Cz[(size_t)r0 * ldc + cg] = v00;
                    Cz[(size_t)r1 * ldc + cg] = v10;
                }
                if (cg + 1 < N) {
                    Cz[(size_t)r0 * ldc + cg + 1] = v01;
                    Cz[(size_t)r1 * ldc + cg + 1] = v11;
                }
            }
        }
    }
}

// ============ gemm128: 128x128 tile, 256 thr, warp-tile 32x64 ===============
__device__ __forceinline__ void issue_tile128(
    const __half* __restrict__ A, int lda,
    const __half* __restrict__ B, int ldb,
    int bm, int bn, int N, int kt,
    __half* as, __half* bs, int tid)
{
#pragma unroll
    for (int i = 0; i < 4; i++) {
        int idx = i * 256 + tid;
        int r = idx >> 3, c = idx & 7;
        uint32_t da = (uint32_t)__cvta_generic_to_shared(as + sw(r, c));
        const __half* pa = A + (size_t)(bm + r) * lda + kt + c * 8;
        asm volatile("cp.async.cg.shared.global [%0], [%1], 16;" :: "r"(da), "l"(pa));
    }
#pragma unroll
    for (int i = 0; i < 4; i++) {
        int idx = i * 256 + tid;
        int r = idx >> 3, c = idx & 7;
        int n = bn + r;
        uint32_t db = (uint32_t)__cvta_generic_to_shared(bs + sw(r, c));
        const __half* pb = B + (size_t)(n < N ? n : 0) * ldb + kt + c * 8;
        int sz = (n < N) ? 16 : 0;
        asm volatile("cp.async.cg.shared.global [%0], [%1], 16, %2;" :: "r"(db), "l"(pb), "r"(sz));
    }
    asm volatile("cp.async.commit_group;");
}

// mode: 1 = fp16 out (+bias), 2 = logits capmap (+bias, rowoff = global row base)
__device__ __forceinline__ void gemm_core128(
    const __half* __restrict__ A, int lda,
    const __half* __restrict__ Bm, int ldb,
    const float* __restrict__ bias,
    float* __restrict__ Cf, __half* __restrict__ Ch,
    int ldc, int M, int N, int K,
    int bm, int by, int mode, int rowoff)
{
    extern __shared__ __half sm[];
    __half* Asm = sm;
    __half* Bsm = sm + STG128 * 128 * 64;

    const int tid = threadIdx.x;
    const int warp = tid >> 5, lane = tid & 31;
    const int wm = warp >> 1, wn = warp & 1;
    const int bn = by * 128;
    const int nk = K / BK;

    float acc[2][8][4];
#pragma unroll
    for (int i = 0; i < 2; i++)
#pragma unroll
        for (int j = 0; j < 8; j++)
#pragma unroll
            for (int q = 0; q < 4; q++) acc[i][j][q] = 0.f;

    const int a_row_l = (lane & 7) + ((lane >> 3) & 1) * 8;
    const int a_chk_l = (lane >> 4) & 1;
    const int b_row_l = (lane & 7) + ((lane >> 4) & 1) * 8;
    const int b_chk_l = (lane >> 3) & 1;

#pragma unroll
    for (int s = 0; s < STG128 - 1; s++) {
        if (s < nk) issue_tile128(A, lda, Bm, ldb, bm, bn, N, s * BK,
                                  Asm + s * 128 * 64, Bsm + s * 128 * 64, tid);
        else asm volatile("cp.async.commit_group;");
    }

    for (int i = 0; i < nk; i++) {
        asm volatile("cp.async.wait_group %0;" :: "n"(STG128 - 2));
        __syncthreads();

        int ntile = i + STG128 - 1;
        if (ntile < nk) {
            int slot = ntile % STG128;
            issue_tile128(A, lda, Bm, ldb, bm, bn, N, ntile * BK,
                          Asm + slot * 128 * 64, Bsm + slot * 128 * 64, tid);
        } else {
            asm volatile("cp.async.commit_group;");
        }

        const __half* at = Asm + (i % STG128) * 128 * 64;
        const __half* bt = Bsm + (i % STG128) * 128 * 64;

#pragma unroll
        for (int ks = 0; ks < 4; ks++) {
            uint32_t a[2][4], b[8][2];
#pragma unroll
            for (int mt = 0; mt < 2; mt++) {
                int row = wm * 32 + mt * 16 + a_row_l;
                uint32_t ad = (uint32_t)__cvta_generic_to_shared(at + sw(row, ks * 2 + a_chk_l));
                asm volatile("ldmatrix.sync.aligned.m8n8.x4.shared.b16 {%0,%1,%2,%3}, [%4];"
                             : "=r"(a[mt][0]), "=r"(a[mt][1]), "=r"(a[mt][2]), "=r"(a[mt][3])
                             : "r"(ad));
            }
#pragma unroll
            for (int ntp = 0; ntp < 4; ntp++) {
                int row = wn * 64 + ntp * 16 + b_row_l;
                uint32_t bd = (uint32_t)__cvta_generic_to_shared(bt + sw(row, ks * 2 + b_chk_l));
                asm volatile("ldmatrix.sync.aligned.m8n8.x4.shared.b16 {%0,%1,%2,%3}, [%4];"
                             : "=r"(b[2 * ntp][0]), "=r"(b[2 * ntp][1]),
                               "=r"(b[2 * ntp + 1][0]), "=r"(b[2 * ntp + 1][1])
                             : "r"(bd));
            }
#pragma unroll
            for (int mt = 0; mt < 2; mt++)
#pragma unroll
                for (int nt = 0; nt < 8; nt++)
                    asm volatile(
                        "mma.sync.aligned.m16n8k16.row.col.f32.f16.f16.f32 "
                        "{%0,%1,%2,%3}, {%4,%5,%6,%7}, {%8,%9}, {%0,%1,%2,%3};"
                        : "+f"(acc[mt][nt][0]), "+f"(acc[mt][nt][1]),
                          "+f"(acc[mt][nt][2]), "+f"(acc[mt][nt][3])
                        : "r"(a[mt][0]), "r"(a[mt][1]), "r"(a[mt][2]), "r"(a[mt][3]),
                          "r"(b[nt][0]), "r"(b[nt][1]));
        }
    }

#pragma unroll
    for (int mt = 0; mt < 2; mt++) {
        int r0 = bm + wm * 32 + mt * 16 + (lane >> 2);
        int r1 = r0 + 8;
#pragma unroll
        for (int nt = 0; nt < 8; nt++) {
            int cg = bn + wn * 64 + nt * 8 + (lane & 3) * 2;
            float bv0 = 0.f, bv1 = 0.f;
            if (bias) {
                if (cg < N) bv0 = bias[cg];
                if (cg + 1 < N) bv1 = bias[cg + 1];
            }
            float v00 = acc[mt][nt][0] + bv0, v01 = acc[mt][nt][1] + bv1;
            float v10 = acc[mt][nt][2] + bv0, v11 = acc[mt][nt][3] + bv1;
            if (mode == 2) {
                int gr0 = rowoff + r0, gr1 = rowoff + r1;
                float* p0 = Cf + (size_t)(gr0 & 63) * ((T_ - 1) * V_) + (size_t)(gr0 >> 6) * V_;
                float* p1 = Cf + (size_t)(gr1 & 63) * ((T_ - 1) * V_) + (size_t)(gr1 >> 6) * V_;
                if (cg < N) {
                    if (r0 < M) p0[cg] = v00;
                    if (r1 < M) p1[cg] = v10;
                }
                if (cg + 1 < N) {
                    if (r0 < M) p0[cg + 1] = v01;
                    if (r1 < M) p1[cg + 1] = v11;
                }
            } else {
                if (cg < N) {
                    if (r0 < M) Ch[(size_t)r0 * ldc + cg] = __float2half(v00);
                    if (r1 < M) Ch[(size_t)r1 * ldc + cg] = __float2half(v10);
                }
                if (cg + 1 < N) {
                    if (r0 < M) Ch[(size_t)r0 * ldc + cg + 1] = __float2half(v01);
                    if (r1 < M) Ch[(size_t)r1 * ldc + cg + 1] = __float2half(v11);
                }
            }
        }
    }
}

// setup: h0c0 [16] + att1 [100] + gatesX [384] + encW [800] = 1300 blocks
#define CB0 16
#define CB1 (CB0 + 25 * 4)
#define CB2 (CB1 + 12 * 32)
#define CB3 (CB2 + 25 * 32)

__global__ void __launch_bounds__(256, 2)
setup_combo(const float* __restrict__ b_eatt)
{
    int bi = blockIdx.x;
    if (bi < CB0) {
        gemm_core64(g_meanh, ENC_, g_Wh0c0, ENC_, nullptr,
                    0, 0, 2048, ENC_, 0, bi, 0, 3);
    } else if (bi < CB1) {
        int i = bi - CB0;
        gemm_core128(g_ench, ENC_, g_Weatt, ENC_, b_eatt, nullptr, g_att1h,
                     A_, B_ * P_, A_, ENC_, (i % 25) * 128, i / 25, 1, 0);
    } else if (bi < CB2) {
        int i = bi - CB1;
        gemm_core128(g_embX, E_, g_Wihx, E_, nullptr, nullptr, g_gatesX,
                     G4_, (T_ - 1) * B_, G4_, E_, (i % 12) * 128, i / 12, 1, 0);
    } else {
        int i = bi - CB2;
        gemm_core128(g_ench, ENC_, g_Wihc, ENC_, nullptr, nullptr, g_encW,
                     G4_, B_ * P_, G4_, ENC_, (i % 25) * 128, i / 25, 1, 0);
    }
}

// per-step fused GEMM: h_t @ [W_hh | W_datt]^T -> ghp partials (split-K 4)
__global__ void __launch_bounds__(256, 2)
hw_kernel(const __half* __restrict__ h)
{
    gemm_core64(h, H_, g_Wcat, H_, g_ghp,
                NCAT, B_ * NCAT, NCAT, H_ / 4, 0, blockIdx.x, blockIdx.y, 0);
}

// ---------------- gatelstm (128 blocks, 2 j's/thread via half2) ------------
__global__ void __launch_bounds__(256)
step_kernel(const float* __restrict__ b_datt,
            const float* __restrict__ W_fatt,
            const float* __restrict__ b_fatt,
            int t)
{
    __shared__ float att2s[A_];
    __shared__ float alpha[P_];

    const int z = blockIdx.x & 1;
    const int b = blockIdx.x >> 1;
    const int tid = threadIdx.x;
    const int warp = tid >> 5, lane = tid & 31;

    // att2 reduce (4 split-K partials)
    for (int a = tid; a < A_; a += 256) {
        float s = b_datt[a];
#pragma unroll
        for (int zz = 0; zz < 4; zz++)
            s += g_ghp[(size_t)zz * B_ * NCAT + b * NCAT + G4_ + a];
        att2s[a] = s;
    }
    __syncthreads();

    const __half2* att1b2 = (const __half2*)(g_att1h + (size_t)b * P_ * A_);
#pragma unroll 7
    for (int p = warp; p < P_; p += 8) {
        float s = 0.f;
#pragma unroll
        for (int a2 = lane; a2 < 256; a2 += 32) {
            float2 v = __half22float2(att1b2[p * 256 + a2]);
            float v0 = v.x + att2s[2 * a2];
            float v1 = v.y + att2s[2 * a2 + 1];
            s += fmaxf(v0, 0.f) * W_fatt[2 * a2] + fmaxf(v1, 0.f) * W_fatt[2 * a2 + 1];
        }
#pragma unroll
        for (int o = 16; o; o >>= 1) s += __shfl_xor_sync(0xffffffffu, s, o);
        if (lane == 0) alpha[p] = s + b_fatt[0];
    }
    __syncthreads();

    if (warp == 0) {
        float v0 = (lane < P_) ? alpha[lane] : -1e30f;
        float v1 = (lane + 32 < P_) ? alpha[lane + 32] : -1e30f;
        float m = fmaxf(v0, v1);
#pragma unroll
        for (int o = 16; o; o >>= 1) m = fmaxf(m, __shfl_xor_sync(0xffffffffu, m, o));
        float e0 = (lane < P_) ? __expf(v0 - m) : 0.f;
        float e1 = (lane + 32 < P_) ? __expf(v1 - m) : 0.f;
        float s = e0 + e1;
#pragma unroll
        for (int o = 16; o; o >>= 1) s += __shfl_xor_sync(0xffffffffu, s, o);
        float inv = 1.0f / s;
        if (lane < P_) alpha[lane] = e0 * inv;
        if (lane + 32 < P_) alpha[lane + 32] = e1 * inv;
    }
    __syncthreads();

    const int j0 = z * 512 + tid * 2;
    const int jj = j0 >> 1;
    const __half2* encWb = (const __half2*)(g_encW + (size_t)b * P_ * G4_);
    float gi0 = 0.f, gi1 = 0.f, gf0 = 0.f, gf1 = 0.f;
    float gg0 = 0.f, gg1 = 0.f, go0 = 0.f, go1 = 0.f;
#pragma unroll 7
    for (int p = 0; p < P_; p++) {
        const __half2* row = encWb + (size_t)p * (G4_ / 2);
        float ap = alpha[p];
        float2 w;
        w = __half22float2(row[jj]);        gi0 += ap * w.x; gi1 += ap * w.y;
        w = __half22float2(row[512 + jj]);  gf0 += ap * w.x; gf1 += ap * w.y;
        w = __half22float2(row[1024 + jj]); gg0 += ap * w.x; gg1 += ap * w.y;
        w = __half22float2(row[1536 + jj]); go0 += ap * w.x; go1 += ap * w.y;
    }
    const __half2* gx2 = (const __half2*)(g_gatesX + ((size_t)t * B_ + b) * G4_);
    {
        float2 w;
        w = __half22float2(gx2[jj]);        gi0 += w.x; gi1 += w.y;
        w = __half22float2(gx2[512 + jj]);  gf0 += w.x; gf1 += w.y;
        w = __half22float2(gx2[1024 + jj]); gg0 += w.x; gg1 += w.y;
        w = __half22float2(gx2[1536 + jj]); go0 += w.x; go1 += w.y;
        float2 bb;
        bb = *(const float2*)(g_bsum + j0);            gi0 += bb.x; gi1 += bb.y;
        bb = *(const float2*)(g_bsum + H_ + j0);       gf0 += bb.x; gf1 += bb.y;
        bb = *(const float2*)(g_bsum + 2 * H_ + j0);   gg0 += bb.x; gg1 += bb.y;
        bb = *(const float2*)(g_bsum + 3 * H_ + j0);   go0 += bb.x; go1 += bb.y;
    }
#pragma unroll
    for (int zz = 0; zz < 4; zz++) {
        const float* gp = g_ghp + (size_t)zz * B_ * NCAT + b * NCAT;
        float2 q;
        q = *(const float2*)(gp + j0);          gi0 += q.x; gi1 += q.y;
        q = *(const float2*)(gp + H_ + j0);     gf0 += q.x; gf1 += q.y;
        q = *(const float2*)(gp + 2 * H_ + j0); gg0 += q.x; gg1 += q.y;
        q = *(const float2*)(gp + 3 * H_ + j0); go0 += q.x; go1 += q.y;
    }

    const float* c_cur = g_cbuf + (t & 1) * B_ * H_;
    float* c_nxt = g_cbuf + ((t + 1) & 1) * B_ * H_;
    __half* h_nxt = g_hall + (size_t)(t + 1) * B_ * H_;
    float2 cc = *(const float2*)(c_cur + b * H_ + j0);
    float si0 = 1.f / (1.f + __expf(-gi0)), si1 = 1.f / (1.f + __expf(-gi1));
    float sf0 = 1.f / (1.f + __expf(-gf0)), sf1 = 1.f / (1.f + __expf(-gf1));
    float so0 = 1.f / (1.f + __expf(-go0)), so1 = 1.f / (1.f + __expf(-go1));
    float tg0 = tanhf(gg0), tg1 = tanhf(gg1);
    float c0 = sf0 * cc.x + si0 * tg0;
    float c1 = sf1 * cc.y + si1 * tg1;
    *(float2*)(c_nxt + b * H_ + j0) = make_float2(c0, c1);
    *(__half2*)(h_nxt + b * H_ + j0) =
        __floats2half2_rn(so0 * tanhf(c0), so1 * tanhf(c1));
}

// ---------------- logits chunk: 8 timesteps (512 rows), grid (4, 79) -------
__global__ void __launch_bounds__(256, 2)
logits_chunk(const float* __restrict__ b_out, float* __restrict__ out, int chunk)
{
    gemm_core128(g_hall + (size_t)(1 + chunk * 8) * B_ * H_, H_, g_Wout, H_,
                 b_out, out, nullptr,
                 0, 512, V_, H_, blockIdx.x * 128, blockIdx.y, 2, chunk * 512);
}

// ---------------- host ----------------
extern "C" void kernel_launch(void* const* d_in, const int* in_sizes, int n_in,
                              void* d_out, int out_size)
{
    const float* enc    = (const float*)d_in[0];
    const int*   caps   = (const int*)  d_in[1];
    const float* embed  = (const float*)d_in[2];
    const float* W_eatt = (const float*)d_in[3];
    const float* b_eatt = (const float*)d_in[4];
    const float* W_datt = (const float*)d_in[5];
    const float* b_datt = (const float*)d_in[6];
    const float* W_fatt = (const float*)d_in[7];
    const float* b_fatt = (const float*)d_in[8];
    const float* W_ih   = (const float*)d_in[9];
    const float* b_ih   = (const float*)d_in[10];
    const float* W_hh   = (const float*)d_in[11];
    const float* b_hh   = (const float*)d_in[12];
    const float* W_h0   = (const float*)d_in[13];
    const float* b_h0   = (const float*)d_in[14];
    const float* W_c0   = (const float*)d_in[15];
    const float* b_c0   = (const float*)d_in[16];
    const float* W_out  = (const float*)d_in[17];
    const float* b_out  = (const float*)d_in[18];
    float* out = (float*)d_out;

    cudaFuncSetAttribute(setup_combo, cudaFuncAttributeMaxDynamicSharedMemorySize, SMEM_BYTES);
    cudaFuncSetAttribute(hw_kernel, cudaFuncAttributeMaxDynamicSharedMemorySize, SMEM_BYTES);
    cudaFuncSetAttribute(logits_chunk, cudaFuncAttributeMaxDynamicSharedMemorySize, SMEM_BYTES);

    // one-time host resources (no device memory)
    static cudaStream_t s2 = nullptr;
    static cudaEvent_t ev0 = nullptr, ev1 = nullptr, evj = nullptr;
    if (!s2) {
        cudaStreamCreateWithFlags(&s2, cudaStreamNonBlocking);
        cudaEventCreateWithFlags(&ev0, cudaEventDisableTiming);
        cudaEventCreateWithFlags(&ev1, cudaEventDisableTiming);
        cudaEventCreateWithFlags(&evj, cudaEventDisableTiming);
    }

    void* hall_p = nullptr;
    cudaGetSymbolAddress(&hall_p, g_hall);
    __half* hall = (__half*)hall_p;

    // ---- one-time setup ----
    mean_kernel<<<(B_ * ENC_ + 255) / 256, 256>>>(enc);
    cvt_all<<<(T8 / 4 + 255) / 256, 256>>>(W_out, W_eatt, W_h0, W_c0, enc, W_ih, W_hh,
                                           W_datt, b_h0, b_c0, b_ih, b_hh);
    embx_kernel<<<((T_ - 1) * B_ * E_ / 4 + 255) / 256, 256>>>(caps, embed);

    setup_combo<<<CB3, 256, SMEM_BYTES>>>(b_eatt);

    // ---- recurrent loop: 2 launches per step; logits chunks forked async ----
    for (int t = 0; t < T_ - 1; t++) {
        hw_kernel<<<dim3(36, 4, 1), 256, SMEM_BYTES>>>(hall + (size_t)t * B_ * H_);
        step_kernel<<<128, 256>>>(b_datt, W_fatt, b_fatt, t);

        if (t == 7) {           // h_1..h_8 final -> logits rows 0..7 on side stream
            cudaEventRecord(ev0, 0);
            cudaStreamWaitEvent(s2, ev0, 0);
            logits_chunk<<<dim3(4, 79, 1), 256, SMEM_BYTES, s2>>>(b_out, out, 0);
        } else if (t == 15) {   // h_9..h_16 final -> logits rows 8..15 on side stream
            cudaEventRecord(ev1, 0);
            cudaStreamWaitEvent(s2, ev1, 0);
            logits_chunk<<<dim3(4, 79, 1), 256, SMEM_BYTES, s2>>>(b_out, out, 1);
            cudaEventRecord(evj, s2);
        }
    }

    // ---- final chunk (rows 16..23) on main stream; join side stream ----
    logits_chunk<<<dim3(4, 79, 1), 256, SMEM_BYTES>>>(b_out, out, 2);
    cudaStreamWaitEvent(0, evj, 0);
}